// round 1
// baseline (speedup 1.0000x reference)
#include <cuda_runtime.h>

#define EPSF 1.1920929e-07f

constexpr int TILE  = 64;          // output tokens per block
constexpr int HALO  = 10;          // staged leading tokens (need 9 for conv taps)
constexpr int NTOK  = TILE + HALO + 2;   // 76, multiple of 4 for quad processing
constexpr int NCH   = 160;         // 128 key channels + 32 value channels
constexpr int ESTR  = NTOK;        // emb_sh token stride

// shared layout (floats)
constexpr int SM_EMB   = 0;                       // [32][NTOK]
constexpr int SM_PROJ  = 32 * NTOK;               // [NTOK][160]  key(128)|value(32)
constexpr int SM_GATE  = SM_PROJ + NTOK * NCH;    // [TILE][4]
constexpr int SM_FLOATS = SM_GATE + TILE * 4;     // 14848 floats = 59392 B

__device__ __forceinline__ unsigned long long fma2(unsigned long long a,
                                                   unsigned long long b,
                                                   unsigned long long c) {
    unsigned long long d;
    asm("fma.rn.f32x2 %0, %1, %2, %3;" : "=l"(d) : "l"(a), "l"(b), "l"(c));
    return d;
}
__device__ __forceinline__ unsigned long long pack2(float x, float y) {
    unsigned long long r;
    asm("mov.b64 %0, {%1, %2};" : "=l"(r) : "f"(x), "f"(y));
    return r;
}

__global__ void __launch_bounds__(320, 2)
engram_kernel(const float* __restrict__ emb, const float* __restrict__ hid,
              const float* __restrict__ Wv,  const float* __restrict__ bv,
              const float* __restrict__ Wk,  const float* __restrict__ bk,
              const float* __restrict__ n1w, const float* __restrict__ n2w,
              const float* __restrict__ cnw, const float* __restrict__ cvw,
              float* __restrict__ out, int T)
{
    extern __shared__ float sm[];
    float* emb_sh  = sm + SM_EMB;
    float* proj_sh = sm + SM_PROJ;
    float* gate_sh = sm + SM_GATE;

    const int tid        = threadIdx.x;
    const int b          = blockIdx.y;
    const int tile_start = blockIdx.x * TILE;
    const long base_tok  = (long)b * T + tile_start;   // global token of tile start

    // ---- stage embeddings transposed: emb_sh[d][tok] ----
    for (int idx = tid; idx < 32 * NTOK; idx += 320) {
        int tok = idx >> 5;
        int d   = idx & 31;
        int gt  = tile_start - HALO + tok;
        float val = 0.f;
        if (tok < TILE + HALO && gt >= 0)
            val = emb[(base_tok - HALO + tok) * 32 + d];
        emb_sh[d * ESTR + tok] = val;
    }

    // ---- per-thread projection weights (packed f32x2, duplicated halves) ----
    const int ch      = tid % NCH;      // output channel
    const int tokhalf = tid / NCH;      // token-range half (0 or 1)
    unsigned long long w2[32];
    unsigned long long bias2;
    {
        const float* wrow;
        float bias;
        if (ch < 128) { wrow = Wk + ch * 32;        bias = bk[ch];       }
        else          { wrow = Wv + (ch - 128) * 32; bias = bv[ch - 128]; }
#pragma unroll
        for (int j = 0; j < 8; j++) {
            float4 f = ((const float4*)wrow)[j];
            w2[4*j+0] = pack2(f.x, f.x);
            w2[4*j+1] = pack2(f.y, f.y);
            w2[4*j+2] = pack2(f.z, f.z);
            w2[4*j+3] = pack2(f.w, f.w);
        }
        bias2 = pack2(bias, bias);
    }
    __syncthreads();

    // ---- Phase A: projections, 4 tokens / iteration via f32x2 FMA ----
    {
        const int qbase = tokhalf ? 10 : 0;
        const int nq    = tokhalf ? 9  : 10;     // 19 quads = 76 tokens
        for (int q = 0; q < nq; q++) {
            const int t0 = (qbase + q) * 4;
            unsigned long long acc0 = bias2, acc1 = bias2;
#pragma unroll
            for (int d = 0; d < 32; d++) {
                ulonglong2 e = *(const ulonglong2*)&emb_sh[d * ESTR + t0];
                acc0 = fma2(e.x, w2[d], acc0);
                acc1 = fma2(e.y, w2[d], acc1);
            }
            float2 a0 = *(float2*)&acc0;
            float2 a1 = *(float2*)&acc1;
            proj_sh[(t0 + 0) * NCH + ch] = a0.x;
            proj_sh[(t0 + 1) * NCH + ch] = a0.y;
            proj_sh[(t0 + 2) * NCH + ch] = a1.x;
            proj_sh[(t0 + 3) * NCH + ch] = a1.y;
        }
    }
    __syncthreads();

    const int wid  = tid >> 5;
    const int lane = tid & 31;

    // ---- Phase B: norms + gate; x_norm overwrites key slot in-place ----
    {
        const int NITEMS = (TILE + HALO) * 4;   // 296 (tok, group) items
        for (int j = wid; j < NITEMS; j += 10) {
            const int tok = j >> 2;
            const int g   = j & 3;
            const int gt  = tile_start - HALO + tok;
            const int kidx = tok * NCH + g * 32 + lane;
            if (gt < 0) { proj_sh[kidx] = 0.f; continue; }   // causal zero-pad

            const float n1 = n1w[g * 32 + lane];
            const float n2 = n2w[g * 32 + lane];
            const float cn = cnw[g * 32 + lane];
            const float k  = proj_sh[kidx];
            const float v  = proj_sh[tok * NCH + 128 + lane];
            const float h  = hid[((base_tok - HALO + tok) * 4 + g) * 32 + lane];

            float skk = k * k;
            float shh = h * h;
            float skh = (k * n1) * (h * n2);
            float svv = v * v;
#pragma unroll
            for (int off = 16; off; off >>= 1) {
                skk += __shfl_xor_sync(0xffffffffu, skk, off);
                shh += __shfl_xor_sync(0xffffffffu, shh, off);
                skh += __shfl_xor_sync(0xffffffffu, skh, off);
                svv += __shfl_xor_sync(0xffffffffu, svv, off);
            }
            const float rs1 = rsqrtf(skk * (1.f / 32.f) + EPSF);
            const float rs2 = rsqrtf(shh * (1.f / 32.f) + EPSF);
            const float dot = skh * rs1 * rs2 * 0.17677669529663687f; // /sqrt(32)
            const float sq  = sqrtf(fmaxf(fabsf(dot), 1e-6f));
            const float gs  = (dot > 0.f) ? sq : ((dot < 0.f) ? -sq : 0.f);
            const float gate = 1.f / (1.f + __expf(-gs));
            const float gated = gate * v;
            // sum(gated^2) = gate^2 * sum(v^2)  -> reuse svv, no extra reduction
            const float xn = gated * rsqrtf(gate * gate * svv * (1.f / 32.f) + EPSF) * cn;
            proj_sh[kidx] = xn;
            if (tok >= HALO && lane == 0)
                gate_sh[(tok - HALO) * 4 + g] = gate;
        }
    }
    __syncthreads();

    // ---- Phase C: dilated causal depthwise conv + SiLU + residual ----
    {
        const int NITEMS = TILE * 4;            // 256 (token, group) items
        for (int j = wid; j < NITEMS; j += 10) {
            const int mt  = j >> 2;             // 0..63
            const int g   = j & 3;
            const int tok = mt + HALO;
            const int base = g * 32 + lane;
            const float4 cw = ((const float4*)cvw)[base];
            float y = cw.x * proj_sh[(tok - 9) * NCH + base]
                    + cw.y * proj_sh[(tok - 6) * NCH + base]
                    + cw.z * proj_sh[(tok - 3) * NCH + base]
                    + cw.w * proj_sh[(tok    ) * NCH + base];
            const float gate = gate_sh[mt * 4 + g];
            const float v    = proj_sh[tok * NCH + 128 + lane];
            const float sil  = y / (1.f + __expf(-y));
            out[((base_tok + mt) * 4 + g) * 32 + lane] = gate * v + sil;
        }
    }
}

extern "C" void kernel_launch(void* const* d_in, const int* in_sizes, int n_in,
                              void* d_out, int out_size)
{
    const float* emb = (const float*)d_in[0];
    const float* hid = (const float*)d_in[1];
    const float* Wv  = (const float*)d_in[2];
    const float* bv  = (const float*)d_in[3];
    const float* Wk  = (const float*)d_in[4];
    const float* bk  = (const float*)d_in[5];
    const float* n1w = (const float*)d_in[6];
    const float* n2w = (const float*)d_in[7];
    const float* cnw = (const float*)d_in[8];
    const float* cvw = (const float*)d_in[9];
    float* out = (float*)d_out;

    const int T = 8192;
    const int B = in_sizes[0] / (T * 32);
    const size_t smem = SM_FLOATS * sizeof(float);   // 59392 B

    cudaFuncSetAttribute(engram_kernel,
                         cudaFuncAttributeMaxDynamicSharedMemorySize, (int)smem);

    dim3 grid(T / TILE, B);
    engram_kernel<<<grid, 320, smem>>>(emb, hid, Wv, bv, Wk, bk,
                                       n1w, n2w, cnw, cvw, out, T);
}

// round 3
// speedup vs baseline: 1.9137x; 1.9137x over previous
#include <cuda_runtime.h>

#define EPSF 1.1920929e-07f
typedef unsigned long long ull;

constexpr int TILE  = 64;
constexpr int HALO  = 10;
constexpr int NTOK  = 76;          // TILE + HALO + 2 (quad multiple)
constexpr int NGATE = 74;          // TILE + HALO
constexpr int ESTR  = 76;          // emb_sh token stride
constexpr int KSTR  = 130;         // key row stride (2 mod 32 -> conflict-free lane=tok)
constexpr int HSTR  = 130;
constexpr int VSTR  = 36;

// shared layout (float offsets)
constexpr int SM_EMB = 0;                     // [32][76]
constexpr int SM_K   = SM_EMB + 32 * NTOK;    // [76][130] keys
constexpr int SM_V   = SM_K + NTOK * KSTR;    // [76][36]  values
constexpr int SM_H   = SM_V + NTOK * VSTR;    // [74][130] hidden (staged)
constexpr int SM_G   = SM_H + NGATE * HSTR;   // [74][4][2] (grr, gate)
constexpr int SM_SVV = SM_G + NGATE * 8;      // [74] (+2 pad)
constexpr int SM_NN  = SM_SVV + 76;           // [128] n1*n2
constexpr int SM_FLOATS = SM_NN + 128;        // 25464 floats = 101856 B

__device__ __forceinline__ ull fma2(ull a, ull b, ull c) {
    ull d; asm("fma.rn.f32x2 %0, %1, %2, %3;" : "=l"(d) : "l"(a), "l"(b), "l"(c)); return d;
}
__device__ __forceinline__ ull mul2(ull a, ull b) {
    ull d; asm("mul.rn.f32x2 %0, %1, %2;" : "=l"(d) : "l"(a), "l"(b)); return d;
}
__device__ __forceinline__ ull add2(ull a, ull b) {
    ull d; asm("add.rn.f32x2 %0, %1, %2;" : "=l"(d) : "l"(a), "l"(b)); return d;
}
__device__ __forceinline__ ull pack2(float x, float y) {
    ull r; asm("mov.b64 %0, {%1, %2};" : "=l"(r) : "f"(x), "f"(y)); return r;
}
__device__ __forceinline__ float lo2(ull a) { float2 f = *(float2*)&a; return f.x; }
__device__ __forceinline__ float hi2(ull a) { float2 f = *(float2*)&a; return f.y; }

__global__ void __launch_bounds__(320, 2)
engram_kernel(const float* __restrict__ emb, const float* __restrict__ hid,
              const float* __restrict__ Wv,  const float* __restrict__ bv,
              const float* __restrict__ Wk,  const float* __restrict__ bk,
              const float* __restrict__ n1w, const float* __restrict__ n2w,
              const float* __restrict__ cnw, const float* __restrict__ cvw,
              float* __restrict__ out, int T)
{
    extern __shared__ float sm[];
    const int tid        = threadIdx.x;
    const int b          = blockIdx.y;
    const int tile_start = blockIdx.x * TILE;
    const long base_tok  = (long)b * T + tile_start;

    // ---- stage: emb transposed, hid rows, nn ----
    for (int idx = tid; idx < 32 * NTOK; idx += 320) {
        int tok = idx >> 5, d = idx & 31;
        int gt  = tile_start - HALO + tok;
        float val = 0.f;
        if (tok < TILE + HALO && gt >= 0)
            val = emb[(base_tok - HALO + tok) * 32 + d];
        sm[SM_EMB + d * ESTR + tok] = val;
    }
    for (int i4 = tid; i4 < NGATE * 32; i4 += 320) {     // 74 rows x 32 float4
        int tok = i4 >> 5, q = i4 & 31;
        int gt  = tile_start - HALO + tok;
        float4 val = make_float4(0.f, 0.f, 0.f, 0.f);
        if (gt >= 0)
            val = ((const float4*)hid)[(base_tok - HALO + tok) * 32 + q];
        float* dst = sm + SM_H + tok * HSTR + q * 4;
        *(float2*)(dst)     = make_float2(val.x, val.y);
        *(float2*)(dst + 2) = make_float2(val.z, val.w);
    }
    if (tid < 128) sm[SM_NN + tid] = n1w[tid] * n2w[tid];

    // ---- per-thread projection weights ----
    const int ch      = tid % 160;
    const int tokhalf = tid / 160;
    ull w2[32], bias2;
    {
        const float* wrow; float bias;
        if (ch < 128) { wrow = Wk + ch * 32;         bias = bk[ch];       }
        else          { wrow = Wv + (ch - 128) * 32; bias = bv[ch - 128]; }
#pragma unroll
        for (int j = 0; j < 8; j++) {
            float4 f = ((const float4*)wrow)[j];
            w2[4*j+0] = pack2(f.x, f.x); w2[4*j+1] = pack2(f.y, f.y);
            w2[4*j+2] = pack2(f.z, f.z); w2[4*j+3] = pack2(f.w, f.w);
        }
        bias2 = pack2(bias, bias);
    }
    __syncthreads();

    // ---- Phase A: projections (4 tokens/iter, 4 indep FMA2 chains) ----
    {
        const int qbase = tokhalf ? 10 : 0;
        const int nq    = tokhalf ? 9  : 10;
        for (int q = 0; q < nq; q++) {
            const int t0 = (qbase + q) * 4;
            ull a0 = bias2, a1 = bias2, b0 = 0ull, b1 = 0ull;
#pragma unroll
            for (int d = 0; d < 16; d++) {
                ulonglong2 e = *(const ulonglong2*)&sm[SM_EMB + d * ESTR + t0];
                a0 = fma2(e.x, w2[d], a0);
                a1 = fma2(e.y, w2[d], a1);
            }
#pragma unroll
            for (int d = 16; d < 32; d++) {
                ulonglong2 e = *(const ulonglong2*)&sm[SM_EMB + d * ESTR + t0];
                b0 = fma2(e.x, w2[d], b0);
                b1 = fma2(e.y, w2[d], b1);
            }
            ull acc0 = add2(a0, b0), acc1 = add2(a1, b1);
            float2 r0 = *(float2*)&acc0, r1 = *(float2*)&acc1;
            if (ch < 128) {   // warp-uniform branch
                sm[SM_K + (t0 + 0) * KSTR + ch] = r0.x;
                sm[SM_K + (t0 + 1) * KSTR + ch] = r0.y;
                sm[SM_K + (t0 + 2) * KSTR + ch] = r1.x;
                sm[SM_K + (t0 + 3) * KSTR + ch] = r1.y;
            } else {
                const int vc = ch - 128;
                sm[SM_V + (t0 + 0) * VSTR + vc] = r0.x;
                sm[SM_V + (t0 + 1) * VSTR + vc] = r0.y;
                sm[SM_V + (t0 + 2) * VSTR + vc] = r1.x;
                sm[SM_V + (t0 + 3) * VSTR + vc] = r1.y;
            }
        }
    }
    __syncthreads();

    // ---- Phase B: per-(tok,g) sums, no cross-lane reduction ----
    const int bg   = (tid < 296) ? tid / 74 : 0;
    const int btok = (tid < 296) ? tid - bg * 74 : 0;
    const int bgt  = tile_start - HALO + btok;
    ull skk2 = 0ull, shh2 = 0ull, skh2 = 0ull;
    if (tid < 296 && bgt >= 0) {
        const float* kp = sm + SM_K + btok * KSTR + bg * 32;
        const float* hp = sm + SM_H + btok * HSTR + bg * 32;
        const float* np = sm + SM_NN + bg * 32;
#pragma unroll
        for (int c = 0; c < 32; c += 2) {
            ull k2 = *(const ull*)(kp + c);
            ull h2 = *(const ull*)(hp + c);
            ull n2 = *(const ull*)(np + c);
            skk2 = fma2(k2, k2, skk2);
            shh2 = fma2(h2, h2, shh2);
            skh2 = fma2(mul2(k2, h2), n2, skh2);
        }
    }
    if (tid < 74) {                       // svv: g-independent, once per token
        ull svv2 = 0ull;
        const float* vp = sm + SM_V + tid * VSTR;
#pragma unroll
        for (int c = 0; c < 32; c += 2) {
            ull v2 = *(const ull*)(vp + c);
            svv2 = fma2(v2, v2, svv2);
        }
        sm[SM_SVV + tid] = lo2(svv2) + hi2(svv2);
    }
    __syncthreads();

    if (tid < 296) {
        float grr = 0.f, gate = 0.f;
        if (bgt >= 0) {
            const float skk = lo2(skk2) + hi2(skk2);
            const float shh = lo2(shh2) + hi2(shh2);
            const float skh = lo2(skh2) + hi2(skh2);
            const float svv = sm[SM_SVV + btok];
            const float rs1 = rsqrtf(skk * (1.f/32.f) + EPSF);
            const float rs2 = rsqrtf(shh * (1.f/32.f) + EPSF);
            const float dot = skh * rs1 * rs2 * 0.17677669529663687f;
            const float sq  = sqrtf(fmaxf(fabsf(dot), 1e-6f));
            const float gs  = (dot > 0.f) ? sq : ((dot < 0.f) ? -sq : 0.f);
            gate = 1.f / (1.f + __expf(-gs));
            grr  = gate * rsqrtf(gate * gate * svv * (1.f/32.f) + EPSF);
        }
        sm[SM_G + btok * 8 + bg * 2 + 0] = grr;
        sm[SM_G + btok * 8 + bg * 2 + 1] = gate;
    }
    __syncthreads();

    // ---- Phase C: conv + SiLU + residual. Warp per token, lane covers 4 ch ----
    {
        const int wid  = tid >> 5, lane = tid & 31;
        const int g    = lane >> 3;
        const int c0   = (lane & 7) * 4;
        const int chb  = g * 32 + c0;
        // transpose conv weights into tap-pairs (hoisted)
        float4 cw0 = ((const float4*)cvw)[chb + 0];
        float4 cw1 = ((const float4*)cvw)[chb + 1];
        float4 cw2 = ((const float4*)cvw)[chb + 2];
        float4 cw3 = ((const float4*)cvw)[chb + 3];
        ull t9a = pack2(cw0.x, cw1.x), t9b = pack2(cw2.x, cw3.x);
        ull t6a = pack2(cw0.y, cw1.y), t6b = pack2(cw2.y, cw3.y);
        ull t3a = pack2(cw0.z, cw1.z), t3b = pack2(cw2.z, cw3.z);
        ull t0a = pack2(cw0.w, cw1.w), t0b = pack2(cw2.w, cw3.w);
        ull cna = pack2(cnw[chb], cnw[chb+1]), cnb = pack2(cnw[chb+2], cnw[chb+3]);

        for (int mt = wid; mt < TILE; mt += 10) {
            const int tok = mt + HALO;
            const float* gp = sm + SM_G;
            const float grr9 = gp[(tok-9)*8 + g*2], grr6 = gp[(tok-6)*8 + g*2];
            const float grr3 = gp[(tok-3)*8 + g*2], grr0 = gp[(tok  )*8 + g*2];
            const float gate = gp[tok*8 + g*2 + 1];
            const ulonglong2 v9 = *(const ulonglong2*)&sm[SM_V + (tok-9)*VSTR + c0];
            const ulonglong2 v6 = *(const ulonglong2*)&sm[SM_V + (tok-6)*VSTR + c0];
            const ulonglong2 v3 = *(const ulonglong2*)&sm[SM_V + (tok-3)*VSTR + c0];
            const ulonglong2 v0 = *(const ulonglong2*)&sm[SM_V + (tok  )*VSTR + c0];
            const ull g92 = pack2(grr9, grr9), g62 = pack2(grr6, grr6);
            const ull g32 = pack2(grr3, grr3), g02 = pack2(grr0, grr0);
            ull ya = mul2(mul2(t9a, v9.x), g92);
            ull yb = mul2(mul2(t9b, v9.y), g92);
            ya = fma2(mul2(t6a, v6.x), g62, ya);
            yb = fma2(mul2(t6b, v6.y), g62, yb);
            ya = fma2(mul2(t3a, v3.x), g32, ya);
            yb = fma2(mul2(t3b, v3.y), g32, yb);
            ya = fma2(mul2(t0a, v0.x), g02, ya);
            yb = fma2(mul2(t0b, v0.y), g02, yb);
            ya = mul2(ya, cna);
            yb = mul2(yb, cnb);
            const float y0 = lo2(ya), y1 = hi2(ya), y2 = lo2(yb), y3 = hi2(yb);
            const float s0 = y0 / (1.f + __expf(-y0));
            const float s1 = y1 / (1.f + __expf(-y1));
            const float s2 = y2 / (1.f + __expf(-y2));
            const float s3 = y3 / (1.f + __expf(-y3));
            float4 o;
            o.x = fmaf(gate, lo2(v0.x), s0);
            o.y = fmaf(gate, hi2(v0.x), s1);
            o.z = fmaf(gate, lo2(v0.y), s2);
            o.w = fmaf(gate, hi2(v0.y), s3);
            ((float4*)out)[(((base_tok + mt) * 4 + g) * 32 + c0) >> 2] = o;
        }
    }
}

extern "C" void kernel_launch(void* const* d_in, const int* in_sizes, int n_in,
                              void* d_out, int out_size)
{
    const float* emb = (const float*)d_in[0];
    const float* hid = (const float*)d_in[1];
    const float* Wv  = (const float*)d_in[2];
    const float* bv  = (const float*)d_in[3];
    const float* Wk  = (const float*)d_in[4];
    const float* bk  = (const float*)d_in[5];
    const float* n1w = (const float*)d_in[6];
    const float* n2w = (const float*)d_in[7];
    const float* cnw = (const float*)d_in[8];
    const float* cvw = (const float*)d_in[9];
    float* out = (float*)d_out;

    const int T = 8192;
    const int B = in_sizes[0] / (T * 32);
    const size_t smem = SM_FLOATS * sizeof(float);   // 101856 B

    cudaFuncSetAttribute(engram_kernel,
                         cudaFuncAttributeMaxDynamicSharedMemorySize, (int)smem);

    dim3 grid(T / TILE, B);
    engram_kernel<<<grid, 320, smem>>>(emb, hid, Wv, bv, Wk, bk,
                                       n1w, n2w, cnw, cvw, out, T);
}

// round 4
// speedup vs baseline: 2.1886x; 1.1437x over previous
#include <cuda_runtime.h>

#define EPSF 1.1920929e-07f
typedef unsigned long long ull;

constexpr int TILE  = 64;
constexpr int HALO  = 10;
constexpr int NTOK  = 76;          // TILE + HALO + 2 (quad multiple)
constexpr int NGATE = 74;          // TILE + HALO
constexpr int ESTR  = 76;          // emb_sh token stride (degree-4 STS, LDS.128-aligned)
constexpr int KSTR  = 132;         // 16B-aligned rows for vector LDS
constexpr int HSTR  = 132;
constexpr int VSTR  = 36;

// shared layout (float offsets)
constexpr int SM_EMB = 0;                     // [32][76]
constexpr int SM_K   = SM_EMB + 32 * NTOK;    // [76][132] keys
constexpr int SM_V   = SM_K + NTOK * KSTR;    // [76][36]  values
constexpr int SM_H   = SM_V + NTOK * VSTR;    // [74][132] hidden (cp.async)
constexpr int SM_G   = SM_H + NGATE * HSTR;   // [74][4][2] (grr, gate)
constexpr int SM_NN  = SM_G + NGATE * 8;      // [128] n1*n2
constexpr int SM_FLOATS = SM_NN + 128;        // 25688 floats = 102752 B

__device__ __forceinline__ ull fma2(ull a, ull b, ull c) {
    ull d; asm("fma.rn.f32x2 %0, %1, %2, %3;" : "=l"(d) : "l"(a), "l"(b), "l"(c)); return d;
}
__device__ __forceinline__ ull mul2(ull a, ull b) {
    ull d; asm("mul.rn.f32x2 %0, %1, %2;" : "=l"(d) : "l"(a), "l"(b)); return d;
}
__device__ __forceinline__ ull add2(ull a, ull b) {
    ull d; asm("add.rn.f32x2 %0, %1, %2;" : "=l"(d) : "l"(a), "l"(b)); return d;
}
__device__ __forceinline__ ull pack2(float x, float y) {
    ull r; asm("mov.b64 %0, {%1, %2};" : "=l"(r) : "f"(x), "f"(y)); return r;
}
__device__ __forceinline__ float lo2(ull a) { float2 f = *(float2*)&a; return f.x; }
__device__ __forceinline__ float hi2(ull a) { float2 f = *(float2*)&a; return f.y; }

__global__ void __launch_bounds__(320, 2)
engram_kernel(const float* __restrict__ emb, const float* __restrict__ hid,
              const float* __restrict__ Wv,  const float* __restrict__ bv,
              const float* __restrict__ Wk,  const float* __restrict__ bk,
              const float* __restrict__ n1w, const float* __restrict__ n2w,
              const float* __restrict__ cnw, const float* __restrict__ cvw,
              float* __restrict__ out, int T)
{
    extern __shared__ float sm[];
    const int tid        = threadIdx.x;
    const int b          = blockIdx.y;
    const int tile_start = blockIdx.x * TILE;
    const long base_tok  = (long)b * T + tile_start;

    // ---- async prefetch of hidden_states into SM_H (waited after Phase A) ----
    {
        unsigned hbase;
        asm("{ .reg .u64 t; cvta.to.shared.u64 t, %1; cvt.u32.u64 %0, t; }"
            : "=r"(hbase) : "l"(sm + SM_H));
        for (int i4 = tid; i4 < NGATE * 32; i4 += 320) {
            int tok = i4 >> 5, q = i4 & 31;
            int gt  = tile_start - HALO + tok;
            const float* src = hid + ((base_tok - HALO + tok) << 7) + q * 4;
            unsigned dst = hbase + (unsigned)(tok * HSTR + q * 4) * 4u;
            int ssz = (gt >= 0) ? 16 : 0;
            asm volatile("cp.async.cg.shared.global [%0], [%1], 16, %2;"
                         :: "r"(dst), "l"(src), "r"(ssz));
        }
        asm volatile("cp.async.commit_group;");
    }

    // ---- stage emb transposed + nn ----
    for (int idx = tid; idx < 32 * NTOK; idx += 320) {
        int tok = idx >> 5, d = idx & 31;
        int gt  = tile_start - HALO + tok;
        float val = 0.f;
        if (tok < TILE + HALO && gt >= 0)
            val = emb[(base_tok - HALO + tok) * 32 + d];
        sm[SM_EMB + d * ESTR + tok] = val;
    }
    if (tid < 128) sm[SM_NN + tid] = n1w[tid] * n2w[tid];

    // ---- per-thread projection weights ----
    const int ch      = tid % 160;
    const int tokhalf = tid / 160;
    ull w2[32], bias2;
    {
        const float* wrow; float bias;
        if (ch < 128) { wrow = Wk + ch * 32;         bias = bk[ch];       }
        else          { wrow = Wv + (ch - 128) * 32; bias = bv[ch - 128]; }
#pragma unroll
        for (int j = 0; j < 8; j++) {
            float4 f = ((const float4*)wrow)[j];
            w2[4*j+0] = pack2(f.x, f.x); w2[4*j+1] = pack2(f.y, f.y);
            w2[4*j+2] = pack2(f.z, f.z); w2[4*j+3] = pack2(f.w, f.w);
        }
        bias2 = pack2(bias, bias);
    }
    __syncthreads();

    // ---- Phase A: projections (4 tokens/iter, 4 indep FMA2 chains) ----
    {
        const int qbase = tokhalf ? 10 : 0;
        const int nq    = tokhalf ? 9  : 10;
        for (int q = 0; q < nq; q++) {
            const int t0 = (qbase + q) * 4;
            ull a0 = bias2, a1 = bias2, b0 = 0ull, b1 = 0ull;
#pragma unroll
            for (int d = 0; d < 16; d++) {
                ulonglong2 e = *(const ulonglong2*)&sm[SM_EMB + d * ESTR + t0];
                a0 = fma2(e.x, w2[d], a0);
                a1 = fma2(e.y, w2[d], a1);
            }
#pragma unroll
            for (int d = 16; d < 32; d++) {
                ulonglong2 e = *(const ulonglong2*)&sm[SM_EMB + d * ESTR + t0];
                b0 = fma2(e.x, w2[d], b0);
                b1 = fma2(e.y, w2[d], b1);
            }
            ull acc0 = add2(a0, b0), acc1 = add2(a1, b1);
            float2 r0 = *(float2*)&acc0, r1 = *(float2*)&acc1;
            if (ch < 128) {   // warp-uniform branch
                sm[SM_K + (t0 + 0) * KSTR + ch] = r0.x;
                sm[SM_K + (t0 + 1) * KSTR + ch] = r0.y;
                sm[SM_K + (t0 + 2) * KSTR + ch] = r1.x;
                sm[SM_K + (t0 + 3) * KSTR + ch] = r1.y;
            } else {
                const int vc = ch - 128;
                sm[SM_V + (t0 + 0) * VSTR + vc] = r0.x;
                sm[SM_V + (t0 + 1) * VSTR + vc] = r0.y;
                sm[SM_V + (t0 + 2) * VSTR + vc] = r1.x;
                sm[SM_V + (t0 + 3) * VSTR + vc] = r1.y;
            }
        }
    }
    asm volatile("cp.async.wait_group 0;" ::: "memory");
    __syncthreads();

    // ---- Phase B: per-(tok,g) sums (incl. svv), no cross-lane reduction ----
    if (tid < 296) {
        const int bg   = tid / 74;
        const int btok = tid - bg * 74;
        const int bgt  = tile_start - HALO + btok;
        float grr = 0.f, gate = 0.f;
        if (bgt >= 0) {
            const float* kp = sm + SM_K + btok * KSTR + bg * 32;
            const float* hp = sm + SM_H + btok * HSTR + bg * 32;
            const float* np = sm + SM_NN + bg * 32;
            const float* vp = sm + SM_V + btok * VSTR;
            ull skk2 = 0ull, shh2 = 0ull, skh2 = 0ull, svv2 = 0ull;
#pragma unroll
            for (int c = 0; c < 32; c += 4) {
                ulonglong2 k2 = *(const ulonglong2*)(kp + c);
                ulonglong2 h2 = *(const ulonglong2*)(hp + c);
                ulonglong2 n2 = *(const ulonglong2*)(np + c);
                ulonglong2 v2 = *(const ulonglong2*)(vp + c);
                skk2 = fma2(k2.x, k2.x, skk2);
                shh2 = fma2(h2.x, h2.x, shh2);
                skh2 = fma2(mul2(k2.x, h2.x), n2.x, skh2);
                svv2 = fma2(v2.x, v2.x, svv2);
                skk2 = fma2(k2.y, k2.y, skk2);
                shh2 = fma2(h2.y, h2.y, shh2);
                skh2 = fma2(mul2(k2.y, h2.y), n2.y, skh2);
                svv2 = fma2(v2.y, v2.y, svv2);
            }
            const float skk = lo2(skk2) + hi2(skk2);
            const float shh = lo2(shh2) + hi2(shh2);
            const float skh = lo2(skh2) + hi2(skh2);
            const float svv = lo2(svv2) + hi2(svv2);
            const float rs1 = rsqrtf(skk * (1.f/32.f) + EPSF);
            const float rs2 = rsqrtf(shh * (1.f/32.f) + EPSF);
            const float dot = skh * rs1 * rs2 * 0.17677669529663687f;
            const float sq  = sqrtf(fmaxf(fabsf(dot), 1e-6f));
            const float gs  = (dot > 0.f) ? sq : ((dot < 0.f) ? -sq : 0.f);
            gate = 1.f / (1.f + __expf(-gs));
            grr  = gate * rsqrtf(gate * gate * svv * (1.f/32.f) + EPSF);
        }
        sm[SM_G + btok * 8 + bg * 2 + 0] = grr;
        sm[SM_G + btok * 8 + bg * 2 + 1] = gate;
    }
    __syncthreads();

    // ---- Phase C: conv + SiLU + residual. Warp per token, lane covers 4 ch ----
    {
        const int wid  = tid >> 5, lane = tid & 31;
        const int g    = lane >> 3;
        const int c0   = (lane & 7) * 4;
        const int chb  = g * 32 + c0;
        float4 cw0 = ((const float4*)cvw)[chb + 0];
        float4 cw1 = ((const float4*)cvw)[chb + 1];
        float4 cw2 = ((const float4*)cvw)[chb + 2];
        float4 cw3 = ((const float4*)cvw)[chb + 3];
        ull t9a = pack2(cw0.x, cw1.x), t9b = pack2(cw2.x, cw3.x);
        ull t6a = pack2(cw0.y, cw1.y), t6b = pack2(cw2.y, cw3.y);
        ull t3a = pack2(cw0.z, cw1.z), t3b = pack2(cw2.z, cw3.z);
        ull t0a = pack2(cw0.w, cw1.w), t0b = pack2(cw2.w, cw3.w);
        ull cna = pack2(cnw[chb], cnw[chb+1]), cnb = pack2(cnw[chb+2], cnw[chb+3]);

        for (int mt = wid; mt < TILE; mt += 10) {
            const int tok = mt + HALO;
            const float* gp = sm + SM_G;
            const float grr9 = gp[(tok-9)*8 + g*2], grr6 = gp[(tok-6)*8 + g*2];
            const float grr3 = gp[(tok-3)*8 + g*2], grr0 = gp[(tok  )*8 + g*2];
            const float gate = gp[tok*8 + g*2 + 1];
            const ulonglong2 v9 = *(const ulonglong2*)&sm[SM_V + (tok-9)*VSTR + c0];
            const ulonglong2 v6 = *(const ulonglong2*)&sm[SM_V + (tok-6)*VSTR + c0];
            const ulonglong2 v3 = *(const ulonglong2*)&sm[SM_V + (tok-3)*VSTR + c0];
            const ulonglong2 v0 = *(const ulonglong2*)&sm[SM_V + (tok  )*VSTR + c0];
            const ull g92 = pack2(grr9, grr9), g62 = pack2(grr6, grr6);
            const ull g32 = pack2(grr3, grr3), g02 = pack2(grr0, grr0);
            ull ya = mul2(mul2(t9a, v9.x), g92);
            ull yb = mul2(mul2(t9b, v9.y), g92);
            ya = fma2(mul2(t6a, v6.x), g62, ya);
            yb = fma2(mul2(t6b, v6.y), g62, yb);
            ya = fma2(mul2(t3a, v3.x), g32, ya);
            yb = fma2(mul2(t3b, v3.y), g32, yb);
            ya = fma2(mul2(t0a, v0.x), g02, ya);
            yb = fma2(mul2(t0b, v0.y), g02, yb);
            ya = mul2(ya, cna);
            yb = mul2(yb, cnb);
            const float y0 = lo2(ya), y1 = hi2(ya), y2 = lo2(yb), y3 = hi2(yb);
            const float s0 = y0 / (1.f + __expf(-y0));
            const float s1 = y1 / (1.f + __expf(-y1));
            const float s2 = y2 / (1.f + __expf(-y2));
            const float s3 = y3 / (1.f + __expf(-y3));
            float4 o;
            o.x = fmaf(gate, lo2(v0.x), s0);
            o.y = fmaf(gate, hi2(v0.x), s1);
            o.z = fmaf(gate, lo2(v0.y), s2);
            o.w = fmaf(gate, hi2(v0.y), s3);
            ((float4*)out)[(((base_tok + mt) * 4 + g) * 32 + c0) >> 2] = o;
        }
    }
}

extern "C" void kernel_launch(void* const* d_in, const int* in_sizes, int n_in,
                              void* d_out, int out_size)
{
    const float* emb = (const float*)d_in[0];
    const float* hid = (const float*)d_in[1];
    const float* Wv  = (const float*)d_in[2];
    const float* bv  = (const float*)d_in[3];
    const float* Wk  = (const float*)d_in[4];
    const float* bk  = (const float*)d_in[5];
    const float* n1w = (const float*)d_in[6];
    const float* n2w = (const float*)d_in[7];
    const float* cnw = (const float*)d_in[8];
    const float* cvw = (const float*)d_in[9];
    float* out = (float*)d_out;

    const int T = 8192;
    const int B = in_sizes[0] / (T * 32);
    const size_t smem = SM_FLOATS * sizeof(float);   // 102752 B

    cudaFuncSetAttribute(engram_kernel,
                         cudaFuncAttributeMaxDynamicSharedMemorySize, (int)smem);

    dim3 grid(T / TILE, B);
    engram_kernel<<<grid, 320, smem>>>(emb, hid, Wv, bv, Wk, bk,
                                       n1w, n2w, cnw, cvw, out, T);
}